// round 2
// baseline (speedup 1.0000x reference)
#include <cuda_runtime.h>
#include <math.h>

#define NNODES   20000
#define NEDGES   320000
#define TOTEDGES (NEDGES + NNODES)
#define INCH     128
#define HEADS    8
#define CPH      33
#define DDIM     264      // HEADS * CPH
#define OUTD     132
#define NEG_SLOPE 0.2f

// ---------------- scratch (static device globals; no allocation) ----------------
__device__ float g_bufA[NNODES * DDIM];   // layer output h
__device__ float g_bufB[NNODES * DDIM];   // xh = h @ W
__device__ float g_as[NNODES * HEADS];
__device__ float g_ad[NNODES * HEADS];
__device__ int   g_deg[NNODES];
__device__ int   g_incl[NNODES];
__device__ int   g_part[32];
__device__ int   g_row[NNODES + 1];
__device__ int   g_cursor[NNODES];
__device__ int   g_csr[TOTEDGES];

// ---------------- CSR build ----------------
__global__ void init_kernel() {
    int t = blockIdx.x * blockDim.x + threadIdx.x;
    if (t < NNODES) { g_deg[t] = 1; g_cursor[t] = 0; }  // deg=1 accounts for self loop
}

__global__ void count_kernel(const int* __restrict__ ei) {
    int t = blockIdx.x * blockDim.x + threadIdx.x;
    if (t < NEDGES) atomicAdd(&g_deg[ei[NEDGES + t]], 1);
}

__global__ void scan_chunk_kernel() {
    __shared__ int sh[1024];
    int gid = blockIdx.x * 1024 + threadIdx.x;
    int v = (gid < NNODES) ? g_deg[gid] : 0;
    sh[threadIdx.x] = v;
    __syncthreads();
    for (int off = 1; off < 1024; off <<= 1) {
        int t = (threadIdx.x >= off) ? sh[threadIdx.x - off] : 0;
        __syncthreads();
        sh[threadIdx.x] += t;
        __syncthreads();
    }
    if (gid < NNODES) g_incl[gid] = sh[threadIdx.x];
    if (threadIdx.x == 1023) g_part[blockIdx.x] = sh[1023];
}

__global__ void scan_part_kernel(int nb) {
    if (threadIdx.x == 0 && blockIdx.x == 0) {
        int s = 0;
        for (int i = 0; i < nb; i++) { int t = g_part[i]; g_part[i] = s; s += t; }
    }
}

__global__ void finalize_row_kernel() {
    int t = blockIdx.x * blockDim.x + threadIdx.x;
    if (t < NNODES) g_row[t + 1] = g_incl[t] + g_part[t >> 10];
    if (t == 0) g_row[0] = 0;
}

__global__ void fill_csr_kernel(const int* __restrict__ ei) {
    int t = blockIdx.x * blockDim.x + threadIdx.x;
    if (t < NEDGES) {
        int s = ei[t];
        int d = ei[NEDGES + t];
        int pos = g_row[d] + atomicAdd(&g_cursor[d], 1);
        g_csr[pos] = s;
    } else if (t < TOTEDGES) {
        int v = t - NEDGES;
        int pos = g_row[v] + atomicAdd(&g_cursor[v], 1);
        g_csr[pos] = v;
    }
}

// ---------------- fp32 SGEMM: C[M,Nd] = A[M,K] @ B[K,Nd] (+bias) ----------------
#define BM 64
#define BN 64
#define BK 8

__global__ void sgemm_kernel(const float* __restrict__ A, const float* __restrict__ B,
                             const float* __restrict__ bias, float* __restrict__ C,
                             int M, int K, int Nd)
{
    __shared__ __align__(16) float As[BK][BM];
    __shared__ __align__(16) float Bs[BK][BN];
    int tid = threadIdx.x;
    int tx = tid & 15;        // 0..15  (N dir, 4 cols each)
    int ty = tid >> 4;        // 0..15  (M dir, 4 rows each)
    int row0 = blockIdx.y * BM;
    int col0 = blockIdx.x * BN;

    float acc[4][4];
#pragma unroll
    for (int i = 0; i < 4; i++)
#pragma unroll
        for (int j = 0; j < 4; j++) acc[i][j] = 0.f;

    for (int k0 = 0; k0 < K; k0 += BK) {
        // A tile 64x8 (stored transposed As[k][m])
#pragma unroll
        for (int i = 0; i < 2; i++) {
            int idx = tid + i * 256;
            int r = idx >> 3, c = idx & 7;
            int gr = row0 + r;
            As[c][r] = (gr < M) ? A[(long)gr * K + k0 + c] : 0.f;
        }
        // B tile 8x64
#pragma unroll
        for (int i = 0; i < 2; i++) {
            int idx = tid + i * 256;
            int r = idx >> 6, c = idx & 63;
            int gc = col0 + c;
            Bs[r][c] = (gc < Nd) ? B[(long)(k0 + r) * Nd + gc] : 0.f;
        }
        __syncthreads();
#pragma unroll
        for (int kk = 0; kk < BK; kk++) {
            float4 av = *reinterpret_cast<const float4*>(&As[kk][ty * 4]);
            float4 bv = *reinterpret_cast<const float4*>(&Bs[kk][tx * 4]);
            float a[4] = {av.x, av.y, av.z, av.w};
            float b[4] = {bv.x, bv.y, bv.z, bv.w};
#pragma unroll
            for (int i = 0; i < 4; i++)
#pragma unroll
                for (int j = 0; j < 4; j++) acc[i][j] = fmaf(a[i], b[j], acc[i][j]);
        }
        __syncthreads();
    }

#pragma unroll
    for (int i = 0; i < 4; i++) {
        int gr = row0 + ty * 4 + i;
        if (gr >= M) continue;
#pragma unroll
        for (int j = 0; j < 4; j++) {
            int gc = col0 + tx * 4 + j;
            if (gc < Nd) {
                float v = acc[i][j];
                if (bias) v += bias[gc];
                C[(long)gr * Nd + gc] = v;
            }
        }
    }
}

// ---------------- per-node attention logits: as/ad [N,H] ----------------
__global__ void alpha_kernel(const float* __restrict__ a_src, const float* __restrict__ a_dst)
{
    int t = blockIdx.x * blockDim.x + threadIdx.x;
    if (t >= NNODES * HEADS) return;
    int n = t >> 3;
    int h = t & 7;
    const float* row = g_bufB + (long)n * DDIM + h * CPH;
    const float* s = a_src + h * CPH;
    const float* d = a_dst + h * CPH;
    float ss = 0.f, dd = 0.f;
#pragma unroll
    for (int c = 0; c < CPH; c++) {
        float v = row[c];
        ss += v * s[c];
        dd += v * d[c];
    }
    g_as[t] = ss;
    g_ad[t] = dd;
}

// ---------------- warp-per-destination softmax aggregation + bias + ELU ----------------
__global__ void aggregate_kernel(const float* __restrict__ bias)
{
    int warp = (blockIdx.x * blockDim.x + threadIdx.x) >> 5;
    if (warp >= NNODES) return;
    int lane = threadIdx.x & 31;
    int beg = g_row[warp], end = g_row[warp + 1];

    float adv = (lane < 8) ? g_ad[warp * 8 + lane] : 0.f;

    // pass 1: per-head max (lanes 0..7 own heads 0..7)
    float m = -1e30f;
    for (int i = beg; i < end; i++) {
        int u = g_csr[i];
        if (lane < 8) {
            float e = g_as[u * 8 + lane] + adv;
            e = (e > 0.f) ? e : NEG_SLOPE * e;
            m = fmaxf(m, e);
        }
    }

    int hd[9];
#pragma unroll
    for (int j = 0; j < 9; j++) {
        int ch = lane + 32 * j;
        hd[j] = (ch < DDIM) ? (ch / CPH) : 0;
    }
    float acc[9];
#pragma unroll
    for (int j = 0; j < 9; j++) acc[j] = 0.f;
    float denom = 0.f;

    // pass 2: exp weights + weighted feature accumulation
    for (int i = beg; i < end; i++) {
        int u = g_csr[i];
        float ex = 0.f;
        if (lane < 8) {
            float e = g_as[u * 8 + lane] + adv;
            e = (e > 0.f) ? e : NEG_SLOPE * e;
            ex = __expf(e - m);
            denom += ex;
        }
        const float* xu = g_bufB + (long)u * DDIM;
#pragma unroll
        for (int j = 0; j < 8; j++) {
            float exj = __shfl_sync(0xffffffffu, ex, hd[j]);
            acc[j] = fmaf(xu[lane + 32 * j], exj, acc[j]);
        }
        float ex8 = __shfl_sync(0xffffffffu, ex, hd[8]);
        if (lane < 8) acc[8] = fmaf(xu[lane + 256], ex8, acc[8]);
    }

    // finalize: normalize, bias, ELU
    float* ho = g_bufA + (long)warp * DDIM;
#pragma unroll
    for (int j = 0; j < 9; j++) {
        float dn = __shfl_sync(0xffffffffu, denom, hd[j]);
        int ch = lane + 32 * j;
        if (ch < DDIM) {
            float v = acc[j] / (dn + 1e-16f) + bias[ch];
            v = (v > 0.f) ? v : (__expf(v) - 1.f);
            ho[ch] = v;
        }
    }
}

// ---------------- launch ----------------
extern "C" void kernel_launch(void* const* d_in, const int* in_sizes, int n_in,
                              void* d_out, int out_size)
{
    const float* x  = (const float*)d_in[0];
    const int*   ei = (const int*)d_in[1];
    const float* W[4]   = {(const float*)d_in[2],  (const float*)d_in[6],
                           (const float*)d_in[10], (const float*)d_in[14]};
    const float* Asw[4] = {(const float*)d_in[3],  (const float*)d_in[7],
                           (const float*)d_in[11], (const float*)d_in[15]};
    const float* Adw[4] = {(const float*)d_in[4],  (const float*)d_in[8],
                           (const float*)d_in[12], (const float*)d_in[16]};
    const float* Bw[4]  = {(const float*)d_in[5],  (const float*)d_in[9],
                           (const float*)d_in[13], (const float*)d_in[17]};
    const float* Wh = (const float*)d_in[18];
    const float* bh = (const float*)d_in[19];
    float* out = (float*)d_out;

    float *bufA = nullptr, *bufB = nullptr;
    cudaGetSymbolAddress((void**)&bufA, g_bufA);
    cudaGetSymbolAddress((void**)&bufB, g_bufB);

    // CSR build (per launch; deterministic structure)
    init_kernel<<<(NNODES + 255) / 256, 256>>>();
    count_kernel<<<(NEDGES + 255) / 256, 256>>>(ei);
    scan_chunk_kernel<<<(NNODES + 1023) / 1024, 1024>>>();
    scan_part_kernel<<<1, 32>>>((NNODES + 1023) / 1024);
    finalize_row_kernel<<<(NNODES + 255) / 256, 256>>>();
    fill_csr_kernel<<<(TOTEDGES + 255) / 256, 256>>>(ei);

    const float* hin = x;
    int K = INCH;
    for (int l = 0; l < 4; l++) {
        dim3 g((DDIM + BN - 1) / BN, (NNODES + BM - 1) / BM);
        sgemm_kernel<<<g, 256>>>(hin, W[l], nullptr, bufB, NNODES, K, DDIM);
        alpha_kernel<<<(NNODES * HEADS + 255) / 256, 256>>>(Asw[l], Adw[l]);
        aggregate_kernel<<<(NNODES + 7) / 8, 256>>>(Bw[l]);
        hin = bufA;
        K = DDIM;
    }

    dim3 g2((OUTD + BN - 1) / BN, (NNODES + BM - 1) / BM);
    sgemm_kernel<<<g2, 256>>>(bufA, Wh, bh, out, NNODES, DDIM, OUTD);
}

// round 3
// speedup vs baseline: 1.0026x; 1.0026x over previous
#include <cuda_runtime.h>
#include <math.h>

#define NNODES   20000
#define NEDGES   320000
#define TOTEDGES (NEDGES + NNODES)
#define INCH     128
#define HEADS    8
#define CPH      33
#define DDIM     264      // HEADS * CPH
#define OUTD     132
#define NEG_SLOPE 0.2f

// ---------------- scratch (static device globals; no allocation) ----------------
__device__ float g_bufA[NNODES * DDIM];   // layer output h
__device__ float g_bufB[NNODES * DDIM];   // xh = h @ W
__device__ float g_as[NNODES * HEADS];
__device__ float g_ad[NNODES * HEADS];
__device__ int   g_deg[NNODES];
__device__ int   g_incl[NNODES];
__device__ int   g_part[32];
__device__ int   g_row[NNODES + 1];
__device__ int   g_cursor[NNODES];
__device__ int   g_csr[TOTEDGES];

// ---------------- CSR build ----------------
__global__ void init_kernel() {
    int t = blockIdx.x * blockDim.x + threadIdx.x;
    if (t < NNODES) { g_deg[t] = 1; g_cursor[t] = 0; }  // deg=1 accounts for self loop
}

__global__ void count_kernel(const int* __restrict__ ei) {
    int t = blockIdx.x * blockDim.x + threadIdx.x;
    if (t < NEDGES) atomicAdd(&g_deg[ei[NEDGES + t]], 1);
}

__global__ void scan_chunk_kernel() {
    __shared__ int sh[1024];
    int gid = blockIdx.x * 1024 + threadIdx.x;
    int v = (gid < NNODES) ? g_deg[gid] : 0;
    sh[threadIdx.x] = v;
    __syncthreads();
    for (int off = 1; off < 1024; off <<= 1) {
        int t = (threadIdx.x >= off) ? sh[threadIdx.x - off] : 0;
        __syncthreads();
        sh[threadIdx.x] += t;
        __syncthreads();
    }
    if (gid < NNODES) g_incl[gid] = sh[threadIdx.x];
    if (threadIdx.x == 1023) g_part[blockIdx.x] = sh[1023];
}

__global__ void scan_part_kernel(int nb) {
    if (threadIdx.x == 0 && blockIdx.x == 0) {
        int s = 0;
        for (int i = 0; i < nb; i++) { int t = g_part[i]; g_part[i] = s; s += t; }
    }
}

__global__ void finalize_row_kernel() {
    int t = blockIdx.x * blockDim.x + threadIdx.x;
    if (t < NNODES) g_row[t + 1] = g_incl[t] + g_part[t >> 10];
    if (t == 0) g_row[0] = 0;
}

__global__ void fill_csr_kernel(const int* __restrict__ ei) {
    int t = blockIdx.x * blockDim.x + threadIdx.x;
    if (t < NEDGES) {
        int s = ei[t];
        int d = ei[NEDGES + t];
        int pos = g_row[d] + atomicAdd(&g_cursor[d], 1);
        g_csr[pos] = s;
    } else if (t < TOTEDGES) {
        int v = t - NEDGES;
        int pos = g_row[v] + atomicAdd(&g_cursor[v], 1);
        g_csr[pos] = v;
    }
}

// ---------------- fp32 SGEMM: C[M,Nd] = A[M,K] @ B[K,Nd] (+bias) ----------------
#define BM 64
#define BN 64
#define BK 8

__global__ void sgemm_kernel(const float* __restrict__ A, const float* __restrict__ B,
                             const float* __restrict__ bias, float* __restrict__ C,
                             int M, int K, int Nd)
{
    __shared__ __align__(16) float As[BK][BM];
    __shared__ __align__(16) float Bs[BK][BN];
    int tid = threadIdx.x;
    int tx = tid & 15;        // 0..15  (N dir, 4 cols each)
    int ty = tid >> 4;        // 0..15  (M dir, 4 rows each)
    int row0 = blockIdx.y * BM;
    int col0 = blockIdx.x * BN;

    float acc[4][4];
#pragma unroll
    for (int i = 0; i < 4; i++)
#pragma unroll
        for (int j = 0; j < 4; j++) acc[i][j] = 0.f;

    for (int k0 = 0; k0 < K; k0 += BK) {
        // A tile 64x8 (stored transposed As[k][m])
#pragma unroll
        for (int i = 0; i < 2; i++) {
            int idx = tid + i * 256;
            int r = idx >> 3, c = idx & 7;
            int gr = row0 + r;
            As[c][r] = (gr < M) ? A[(long)gr * K + k0 + c] : 0.f;
        }
        // B tile 8x64
#pragma unroll
        for (int i = 0; i < 2; i++) {
            int idx = tid + i * 256;
            int r = idx >> 6, c = idx & 63;
            int gc = col0 + c;
            Bs[r][c] = (gc < Nd) ? B[(long)(k0 + r) * Nd + gc] : 0.f;
        }
        __syncthreads();
#pragma unroll
        for (int kk = 0; kk < BK; kk++) {
            float4 av = *reinterpret_cast<const float4*>(&As[kk][ty * 4]);
            float4 bv = *reinterpret_cast<const float4*>(&Bs[kk][tx * 4]);
            float a[4] = {av.x, av.y, av.z, av.w};
            float b[4] = {bv.x, bv.y, bv.z, bv.w};
#pragma unroll
            for (int i = 0; i < 4; i++)
#pragma unroll
                for (int j = 0; j < 4; j++) acc[i][j] = fmaf(a[i], b[j], acc[i][j]);
        }
        __syncthreads();
    }

#pragma unroll
    for (int i = 0; i < 4; i++) {
        int gr = row0 + ty * 4 + i;
        if (gr >= M) continue;
#pragma unroll
        for (int j = 0; j < 4; j++) {
            int gc = col0 + tx * 4 + j;
            if (gc < Nd) {
                float v = acc[i][j];
                if (bias) v += bias[gc];
                C[(long)gr * Nd + gc] = v;
            }
        }
    }
}

// ---------------- per-node attention logits: as/ad [N,H] ----------------
__global__ void alpha_kernel(const float* __restrict__ a_src, const float* __restrict__ a_dst)
{
    int t = blockIdx.x * blockDim.x + threadIdx.x;
    if (t >= NNODES * HEADS) return;
    int n = t >> 3;
    int h = t & 7;
    const float* row = g_bufB + (long)n * DDIM + h * CPH;
    const float* s = a_src + h * CPH;
    const float* d = a_dst + h * CPH;
    float ss = 0.f, dd = 0.f;
#pragma unroll
    for (int c = 0; c < CPH; c++) {
        float v = row[c];
        ss += v * s[c];
        dd += v * d[c];
    }
    g_as[t] = ss;
    g_ad[t] = dd;
}

// ---------------- warp-per-destination softmax aggregation + bias + ELU ----------------
__global__ void aggregate_kernel(const float* __restrict__ bias)
{
    int warp = (blockIdx.x * blockDim.x + threadIdx.x) >> 5;
    if (warp >= NNODES) return;
    int lane = threadIdx.x & 31;
    int beg = g_row[warp], end = g_row[warp + 1];

    float adv = (lane < 8) ? g_ad[warp * 8 + lane] : 0.f;

    // pass 1: per-head max (lanes 0..7 own heads 0..7)
    float m = -1e30f;
    for (int i = beg; i < end; i++) {
        int u = g_csr[i];
        if (lane < 8) {
            float e = g_as[u * 8 + lane] + adv;
            e = (e > 0.f) ? e : NEG_SLOPE * e;
            m = fmaxf(m, e);
        }
    }

    int hd[9];
#pragma unroll
    for (int j = 0; j < 9; j++) {
        int ch = lane + 32 * j;
        hd[j] = (ch < DDIM) ? (ch / CPH) : 0;
    }
    float acc[9];
#pragma unroll
    for (int j = 0; j < 9; j++) acc[j] = 0.f;
    float denom = 0.f;

    // pass 2: exp weights + weighted feature accumulation
    for (int i = beg; i < end; i++) {
        int u = g_csr[i];
        float ex = 0.f;
        if (lane < 8) {
            float e = g_as[u * 8 + lane] + adv;
            e = (e > 0.f) ? e : NEG_SLOPE * e;
            ex = __expf(e - m);
            denom += ex;
        }
        const float* xu = g_bufB + (long)u * DDIM;
#pragma unroll
        for (int j = 0; j < 8; j++) {
            float exj = __shfl_sync(0xffffffffu, ex, hd[j]);
            acc[j] = fmaf(xu[lane + 32 * j], exj, acc[j]);
        }
        float ex8 = __shfl_sync(0xffffffffu, ex, hd[8]);
        if (lane < 8) acc[8] = fmaf(xu[lane + 256], ex8, acc[8]);
    }

    // finalize: normalize, bias, ELU
    float* ho = g_bufA + (long)warp * DDIM;
#pragma unroll
    for (int j = 0; j < 9; j++) {
        float dn = __shfl_sync(0xffffffffu, denom, hd[j]);
        int ch = lane + 32 * j;
        if (ch < DDIM) {
            float v = acc[j] / (dn + 1e-16f) + bias[ch];
            v = (v > 0.f) ? v : (__expf(v) - 1.f);
            ho[ch] = v;
        }
    }
}

// ---------------- launch ----------------
extern "C" void kernel_launch(void* const* d_in, const int* in_sizes, int n_in,
                              void* d_out, int out_size)
{
    const float* x  = (const float*)d_in[0];
    const int*   ei = (const int*)d_in[1];
    const float* W[4]   = {(const float*)d_in[2],  (const float*)d_in[6],
                           (const float*)d_in[10], (const float*)d_in[14]};
    const float* Asw[4] = {(const float*)d_in[3],  (const float*)d_in[7],
                           (const float*)d_in[11], (const float*)d_in[15]};
    const float* Adw[4] = {(const float*)d_in[4],  (const float*)d_in[8],
                           (const float*)d_in[12], (const float*)d_in[16]};
    const float* Bw[4]  = {(const float*)d_in[5],  (const float*)d_in[9],
                           (const float*)d_in[13], (const float*)d_in[17]};
    const float* Wh = (const float*)d_in[18];
    const float* bh = (const float*)d_in[19];
    float* out = (float*)d_out;

    float *bufA = nullptr, *bufB = nullptr;
    cudaGetSymbolAddress((void**)&bufA, g_bufA);
    cudaGetSymbolAddress((void**)&bufB, g_bufB);

    // CSR build (per launch; deterministic structure)
    init_kernel<<<(NNODES + 255) / 256, 256>>>();
    count_kernel<<<(NEDGES + 255) / 256, 256>>>(ei);
    scan_chunk_kernel<<<(NNODES + 1023) / 1024, 1024>>>();
    scan_part_kernel<<<1, 32>>>((NNODES + 1023) / 1024);
    finalize_row_kernel<<<(NNODES + 255) / 256, 256>>>();
    fill_csr_kernel<<<(TOTEDGES + 255) / 256, 256>>>(ei);

    const float* hin = x;
    int K = INCH;
    for (int l = 0; l < 4; l++) {
        dim3 g((DDIM + BN - 1) / BN, (NNODES + BM - 1) / BM);
        sgemm_kernel<<<g, 256>>>(hin, W[l], nullptr, bufB, NNODES, K, DDIM);
        alpha_kernel<<<(NNODES * HEADS + 255) / 256, 256>>>(Asw[l], Adw[l]);
        aggregate_kernel<<<(NNODES + 7) / 8, 256>>>(Bw[l]);
        hin = bufA;
        K = DDIM;
    }

    dim3 g2((OUTD + BN - 1) / BN, (NNODES + BM - 1) / BM);
    sgemm_kernel<<<g2, 256>>>(bufA, Wh, bh, out, NNODES, DDIM, OUTD);
}

// round 4
// speedup vs baseline: 1.0030x; 1.0004x over previous
#include <cuda_runtime.h>
#include <math.h>

#define NNODES   20000
#define NEDGES   320000
#define TOTEDGES (NEDGES + NNODES)
#define INCH     128
#define HEADS    8
#define CPH      33
#define DDIM     264      // HEADS * CPH
#define OUTD     132
#define NEG_SLOPE 0.2f

// ---------------- scratch (static device globals; no allocation) ----------------
__device__ float g_bufA[NNODES * DDIM];   // layer output h
__device__ float g_bufB[NNODES * DDIM];   // xh = h @ W
__device__ float g_as[NNODES * HEADS];
__device__ float g_ad[NNODES * HEADS];
__device__ int   g_deg[NNODES];
__device__ int   g_incl[NNODES];
__device__ int   g_part[32];
__device__ int   g_row[NNODES + 1];
__device__ int   g_cursor[NNODES];
__device__ int   g_csr[TOTEDGES];

// ---------------- CSR build ----------------
__global__ void init_kernel() {
    int t = blockIdx.x * blockDim.x + threadIdx.x;
    if (t < NNODES) { g_deg[t] = 1; g_cursor[t] = 0; }  // deg=1 accounts for self loop
}

__global__ void count_kernel(const int* __restrict__ ei) {
    int t = blockIdx.x * blockDim.x + threadIdx.x;
    if (t < NEDGES) atomicAdd(&g_deg[ei[NEDGES + t]], 1);
}

__global__ void scan_chunk_kernel() {
    __shared__ int sh[1024];
    int gid = blockIdx.x * 1024 + threadIdx.x;
    int v = (gid < NNODES) ? g_deg[gid] : 0;
    sh[threadIdx.x] = v;
    __syncthreads();
    for (int off = 1; off < 1024; off <<= 1) {
        int t = (threadIdx.x >= off) ? sh[threadIdx.x - off] : 0;
        __syncthreads();
        sh[threadIdx.x] += t;
        __syncthreads();
    }
    if (gid < NNODES) g_incl[gid] = sh[threadIdx.x];
    if (threadIdx.x == 1023) g_part[blockIdx.x] = sh[1023];
}

__global__ void scan_part_kernel(int nb) {
    if (threadIdx.x == 0 && blockIdx.x == 0) {
        int s = 0;
        for (int i = 0; i < nb; i++) { int t = g_part[i]; g_part[i] = s; s += t; }
    }
}

__global__ void finalize_row_kernel() {
    int t = blockIdx.x * blockDim.x + threadIdx.x;
    if (t < NNODES) g_row[t + 1] = g_incl[t] + g_part[t >> 10];
    if (t == 0) g_row[0] = 0;
}

__global__ void fill_csr_kernel(const int* __restrict__ ei) {
    int t = blockIdx.x * blockDim.x + threadIdx.x;
    if (t < NEDGES) {
        int s = ei[t];
        int d = ei[NEDGES + t];
        int pos = g_row[d] + atomicAdd(&g_cursor[d], 1);
        g_csr[pos] = s;
    } else if (t < TOTEDGES) {
        int v = t - NEDGES;
        int pos = g_row[v] + atomicAdd(&g_cursor[v], 1);
        g_csr[pos] = v;
    }
}

// ---------------- fp32 SGEMM: C[M,Nd] = A[M,K] @ B[K,Nd] (+bias) ----------------
#define BM 64
#define BN 64
#define BK 8

__global__ void sgemm_kernel(const float* __restrict__ A, const float* __restrict__ B,
                             const float* __restrict__ bias, float* __restrict__ C,
                             int M, int K, int Nd)
{
    __shared__ __align__(16) float As[BK][BM];
    __shared__ __align__(16) float Bs[BK][BN];
    int tid = threadIdx.x;
    int tx = tid & 15;        // 0..15  (N dir, 4 cols each)
    int ty = tid >> 4;        // 0..15  (M dir, 4 rows each)
    int row0 = blockIdx.y * BM;
    int col0 = blockIdx.x * BN;

    float acc[4][4];
#pragma unroll
    for (int i = 0; i < 4; i++)
#pragma unroll
        for (int j = 0; j < 4; j++) acc[i][j] = 0.f;

    for (int k0 = 0; k0 < K; k0 += BK) {
        // A tile 64x8 (stored transposed As[k][m])
#pragma unroll
        for (int i = 0; i < 2; i++) {
            int idx = tid + i * 256;
            int r = idx >> 3, c = idx & 7;
            int gr = row0 + r;
            As[c][r] = (gr < M) ? A[(long)gr * K + k0 + c] : 0.f;
        }
        // B tile 8x64
#pragma unroll
        for (int i = 0; i < 2; i++) {
            int idx = tid + i * 256;
            int r = idx >> 6, c = idx & 63;
            int gc = col0 + c;
            Bs[r][c] = (gc < Nd) ? B[(long)(k0 + r) * Nd + gc] : 0.f;
        }
        __syncthreads();
#pragma unroll
        for (int kk = 0; kk < BK; kk++) {
            float4 av = *reinterpret_cast<const float4*>(&As[kk][ty * 4]);
            float4 bv = *reinterpret_cast<const float4*>(&Bs[kk][tx * 4]);
            float a[4] = {av.x, av.y, av.z, av.w};
            float b[4] = {bv.x, bv.y, bv.z, bv.w};
#pragma unroll
            for (int i = 0; i < 4; i++)
#pragma unroll
                for (int j = 0; j < 4; j++) acc[i][j] = fmaf(a[i], b[j], acc[i][j]);
        }
        __syncthreads();
    }

#pragma unroll
    for (int i = 0; i < 4; i++) {
        int gr = row0 + ty * 4 + i;
        if (gr >= M) continue;
#pragma unroll
        for (int j = 0; j < 4; j++) {
            int gc = col0 + tx * 4 + j;
            if (gc < Nd) {
                float v = acc[i][j];
                if (bias) v += bias[gc];
                C[(long)gr * Nd + gc] = v;
            }
        }
    }
}

// ---------------- per-node attention logits: as/ad [N,H] ----------------
__global__ void alpha_kernel(const float* __restrict__ a_src, const float* __restrict__ a_dst)
{
    int t = blockIdx.x * blockDim.x + threadIdx.x;
    if (t >= NNODES * HEADS) return;
    int n = t >> 3;
    int h = t & 7;
    const float* row = g_bufB + (long)n * DDIM + h * CPH;
    const float* s = a_src + h * CPH;
    const float* d = a_dst + h * CPH;
    float ss = 0.f, dd = 0.f;
#pragma unroll
    for (int c = 0; c < CPH; c++) {
        float v = row[c];
        ss += v * s[c];
        dd += v * d[c];
    }
    g_as[t] = ss;
    g_ad[t] = dd;
}

// ---------------- warp-per-destination softmax aggregation + bias + ELU ----------------
__global__ void aggregate_kernel(const float* __restrict__ bias)
{
    int warp = (blockIdx.x * blockDim.x + threadIdx.x) >> 5;
    if (warp >= NNODES) return;
    int lane = threadIdx.x & 31;
    int beg = g_row[warp], end = g_row[warp + 1];

    float adv = (lane < 8) ? g_ad[warp * 8 + lane] : 0.f;

    // pass 1: per-head max (lanes 0..7 own heads 0..7)
    float m = -1e30f;
    for (int i = beg; i < end; i++) {
        int u = g_csr[i];
        if (lane < 8) {
            float e = g_as[u * 8 + lane] + adv;
            e = (e > 0.f) ? e : NEG_SLOPE * e;
            m = fmaxf(m, e);
        }
    }

    int hd[9];
#pragma unroll
    for (int j = 0; j < 9; j++) {
        int ch = lane + 32 * j;
        hd[j] = (ch < DDIM) ? (ch / CPH) : 0;
    }
    float acc[9];
#pragma unroll
    for (int j = 0; j < 9; j++) acc[j] = 0.f;
    float denom = 0.f;

    // pass 2: exp weights + weighted feature accumulation
    for (int i = beg; i < end; i++) {
        int u = g_csr[i];
        float ex = 0.f;
        if (lane < 8) {
            float e = g_as[u * 8 + lane] + adv;
            e = (e > 0.f) ? e : NEG_SLOPE * e;
            ex = __expf(e - m);
            denom += ex;
        }
        const float* xu = g_bufB + (long)u * DDIM;
#pragma unroll
        for (int j = 0; j < 8; j++) {
            float exj = __shfl_sync(0xffffffffu, ex, hd[j]);
            acc[j] = fmaf(xu[lane + 32 * j], exj, acc[j]);
        }
        float ex8 = __shfl_sync(0xffffffffu, ex, hd[8]);
        if (lane < 8) acc[8] = fmaf(xu[lane + 256], ex8, acc[8]);
    }

    // finalize: normalize, bias, ELU
    float* ho = g_bufA + (long)warp * DDIM;
#pragma unroll
    for (int j = 0; j < 9; j++) {
        float dn = __shfl_sync(0xffffffffu, denom, hd[j]);
        int ch = lane + 32 * j;
        if (ch < DDIM) {
            float v = acc[j] / (dn + 1e-16f) + bias[ch];
            v = (v > 0.f) ? v : (__expf(v) - 1.f);
            ho[ch] = v;
        }
    }
}

// ---------------- launch ----------------
extern "C" void kernel_launch(void* const* d_in, const int* in_sizes, int n_in,
                              void* d_out, int out_size)
{
    const float* x  = (const float*)d_in[0];
    const int*   ei = (const int*)d_in[1];
    const float* W[4]   = {(const float*)d_in[2],  (const float*)d_in[6],
                           (const float*)d_in[10], (const float*)d_in[14]};
    const float* Asw[4] = {(const float*)d_in[3],  (const float*)d_in[7],
                           (const float*)d_in[11], (const float*)d_in[15]};
    const float* Adw[4] = {(const float*)d_in[4],  (const float*)d_in[8],
                           (const float*)d_in[12], (const float*)d_in[16]};
    const float* Bw[4]  = {(const float*)d_in[5],  (const float*)d_in[9],
                           (const float*)d_in[13], (const float*)d_in[17]};
    const float* Wh = (const float*)d_in[18];
    const float* bh = (const float*)d_in[19];
    float* out = (float*)d_out;

    float *bufA = nullptr, *bufB = nullptr;
    cudaGetSymbolAddress((void**)&bufA, g_bufA);
    cudaGetSymbolAddress((void**)&bufB, g_bufB);

    // CSR build (per launch; deterministic structure)
    init_kernel<<<(NNODES + 255) / 256, 256>>>();
    count_kernel<<<(NEDGES + 255) / 256, 256>>>(ei);
    scan_chunk_kernel<<<(NNODES + 1023) / 1024, 1024>>>();
    scan_part_kernel<<<1, 32>>>((NNODES + 1023) / 1024);
    finalize_row_kernel<<<(NNODES + 255) / 256, 256>>>();
    fill_csr_kernel<<<(TOTEDGES + 255) / 256, 256>>>(ei);

    const float* hin = x;
    int K = INCH;
    for (int l = 0; l < 4; l++) {
        dim3 g((DDIM + BN - 1) / BN, (NNODES + BM - 1) / BM);
        sgemm_kernel<<<g, 256>>>(hin, W[l], nullptr, bufB, NNODES, K, DDIM);
        alpha_kernel<<<(NNODES * HEADS + 255) / 256, 256>>>(Asw[l], Adw[l]);
        aggregate_kernel<<<(NNODES + 7) / 8, 256>>>(Bw[l]);
        hin = bufA;
        K = DDIM;
    }

    dim3 g2((OUTD + BN - 1) / BN, (NNODES + BM - 1) / BM);
    sgemm_kernel<<<g2, 256>>>(bufA, Wh, bh, out, NNODES, DDIM, OUTD);
}